// round 12
// baseline (speedup 1.0000x reference)
#include <cuda_runtime.h>
#include <math.h>

#define BATCH 8
#define SEQ   2048
#define CH    512
#define MTOT  (BATCH*SEQ)          // 16384
#define SCALE 0.04419417382415922f // 1/sqrt(512)

#define BR 32
#define BC 64

// Scratch for projected q,k,v (device globals: allocation-free per harness rules)
__device__ float g_q[(size_t)MTOT*CH];
__device__ float g_k[(size_t)MTOT*CH];
__device__ float g_v[(size_t)MTOT*CH];

// ---------------------------------------------------------------------------
// Kernel 1: QKV projection.  C_z = x @ W_z + b_z,  z = blockIdx.z in {q,k,v}
// Classic 128x128x8 SGEMM, 256 threads, 8x8 per-thread microtile.
// ---------------------------------------------------------------------------
__global__ __launch_bounds__(256) void qkv_gemm(
    const float* __restrict__ x,
    const float* __restrict__ Wq, const float* __restrict__ bq,
    const float* __restrict__ Wk, const float* __restrict__ bk,
    const float* __restrict__ Wv, const float* __restrict__ bv)
{
    __shared__ float As[8][128];
    __shared__ float Bs[8][128];

    const int z = blockIdx.z;
    const float* W    = (z == 0) ? Wq : (z == 1) ? Wk : Wv;
    const float* bias = (z == 0) ? bq : (z == 1) ? bk : bv;
    float* out        = (z == 0) ? g_q : (z == 1) ? g_k : g_v;

    const int bm = blockIdx.y * 128;
    const int bn = blockIdx.x * 128;
    const int tid = threadIdx.x;
    const int tx = tid & 15;        // 0..15 (col group)
    const int ty = tid >> 4;        // 0..15 (row group)

    const int a_row = tid >> 1;         // 0..127
    const int a_k4  = (tid & 1) * 4;    // 0 or 4
    const int b_k   = tid >> 5;         // 0..7
    const int b_n4  = (tid & 31) * 4;   // 0..124

    float acc[8][8];
    #pragma unroll
    for (int i = 0; i < 8; i++)
        #pragma unroll
        for (int j = 0; j < 8; j++) acc[i][j] = 0.f;

    for (int k0 = 0; k0 < CH; k0 += 8) {
        float4 av  = *(const float4*)&x[(size_t)(bm + a_row)*CH + k0 + a_k4];
        float4 bv4 = *(const float4*)&W[(size_t)(k0 + b_k)*CH + bn + b_n4];
        __syncthreads();   // protect prior-iteration smem reads
        As[a_k4+0][a_row] = av.x;
        As[a_k4+1][a_row] = av.y;
        As[a_k4+2][a_row] = av.z;
        As[a_k4+3][a_row] = av.w;
        *(float4*)&Bs[b_k][b_n4] = bv4;
        __syncthreads();
        #pragma unroll
        for (int k = 0; k < 8; k++) {
            float a[8], bb[8];
            *(float4*)&a[0]  = *(float4*)&As[k][ty*8];
            *(float4*)&a[4]  = *(float4*)&As[k][ty*8+4];
            *(float4*)&bb[0] = *(float4*)&Bs[k][tx*8];
            *(float4*)&bb[4] = *(float4*)&Bs[k][tx*8+4];
            #pragma unroll
            for (int i = 0; i < 8; i++)
                #pragma unroll
                for (int j = 0; j < 8; j++)
                    acc[i][j] += a[i] * bb[j];
        }
    }

    #pragma unroll
    for (int i = 0; i < 8; i++) {
        const int m = bm + ty*8 + i;
        #pragma unroll
        for (int j = 0; j < 8; j += 4) {
            const int n = bn + tx*8 + j;
            float4 o;
            o.x = acc[i][j+0] + bias[n+0];
            o.y = acc[i][j+1] + bias[n+1];
            o.z = acc[i][j+2] + bias[n+2];
            o.w = acc[i][j+3] + bias[n+3];
            *(float4*)&out[(size_t)m*CH + n] = o;
        }
    }
}

// ---------------------------------------------------------------------------
// Kernel 2: flash attention (fp32, causal), Br=32 q-rows per block, Bc=64.
// Q block resident in smem; K streamed in [64][128] d-chunks, V streamed in
// [16][512] j-chunks through a shared buffer. O in registers (2 rows x 32 d
// per thread). Online softmax, 8 threads per row.
// smem: sQ 32*516 | sKV 8256 | sS 32*65 | sM/sL/sA 32 each  = 107776 bytes
// ---------------------------------------------------------------------------
#define SMEM_FLOATS (32*516 + 8256 + 32*65 + 96)
#define SMEM_BYTES  (SMEM_FLOATS * 4)

__global__ __launch_bounds__(256, 2) void attn_kernel(float* __restrict__ out)
{
    extern __shared__ float smem[];
    float* sQ  = smem;                 // [32][516]
    float* sKV = sQ + 32*516;          // 8256 floats (K chunks [64][129] / V chunks [16][516])
    float* sS  = sKV + 8256;           // [32][65]
    float* sM  = sS + 32*65;
    float* sL  = sM + 32;
    float* sA  = sL + 32;

    const int b   = blockIdx.y;
    const int qb  = blockIdx.x;
    const int q0  = qb * BR;
    const int tid = threadIdx.x;

    const float* Qg = g_q + (size_t)b*SEQ*CH;
    const float* Kg = g_k + (size_t)b*SEQ*CH;
    const float* Vg = g_v + (size_t)b*SEQ*CH;

    // Load Q block (scaled by 1/sqrt(d))
    #pragma unroll
    for (int i = 0; i < 16; i++) {
        const int lin = (i*256 + tid) * 4;   // 0..16380
        const int r = lin >> 9;
        const int c = lin & 511;
        float4 v = *(const float4*)&Qg[(size_t)(q0 + r)*CH + c];
        v.x *= SCALE; v.y *= SCALE; v.z *= SCALE; v.w *= SCALE;
        *(float4*)&sQ[r*516 + c] = v;
    }
    if (tid < 32) { sM[tid] = -1e30f; sL[tid] = 0.f; }

    const int rowg = tid >> 4;   // 0..15
    const int colg = tid & 15;   // 0..15
    const int r0 = rowg * 2;

    float O[2][32];
    #pragma unroll
    for (int i = 0; i < 2; i++)
        #pragma unroll
        for (int k = 0; k < 32; k++) O[i][k] = 0.f;

    const int n_tiles = (q0 + BR + BC - 1) / BC;

    for (int t = 0; t < n_tiles; t++) {
        const int j0 = t * BC;
        float acc[2][4];
        #pragma unroll
        for (int i = 0; i < 2; i++)
            #pragma unroll
            for (int j = 0; j < 4; j++) acc[i][j] = 0.f;

        // ---- S = Q K^T accumulated over 4 d-chunks of 128 ----
        for (int cc = 0; cc < 4; cc++) {
            __syncthreads();  // protect prior consumers of sKV
            #pragma unroll
            for (int i = 0; i < 8; i++) {
                const int lin = (i*256 + tid) * 4;
                const int r = lin >> 7;      // /128 -> 0..63
                const int c = lin & 127;
                float4 v = *(const float4*)&Kg[(size_t)(j0 + r)*CH + cc*128 + c];
                float* p = &sKV[r*129 + c];
                p[0] = v.x; p[1] = v.y; p[2] = v.z; p[3] = v.w;
            }
            __syncthreads();
            const float* qb0 = &sQ[r0*516 + cc*128];
            const float* qb1 = qb0 + 516;
            const float* kb  = &sKV[(colg*4)*129];
            #pragma unroll 4
            for (int c = 0; c < 128; c++) {
                const float a0 = qb0[c];
                const float a1 = qb1[c];
                #pragma unroll
                for (int jj = 0; jj < 4; jj++) {
                    const float bb = kb[jj*129 + c];
                    acc[0][jj] += a0 * bb;
                    acc[1][jj] += a1 * bb;
                }
            }
        }

        // ---- causal mask + stage S ----
        #pragma unroll
        for (int i = 0; i < 2; i++) {
            const int qg = q0 + r0 + i;
            #pragma unroll
            for (int jj = 0; jj < 4; jj++) {
                const int jgl = j0 + colg*4 + jj;
                float v = acc[i][jj];
                if (jgl > qg) v = -1e30f;
                sS[(r0+i)*65 + colg*4 + jj] = v;
            }
        }
        __syncthreads();

        // ---- online softmax: 8 threads per row ----
        {
            const int row = tid >> 3;
            const int g   = tid & 7;
            float vals[8];
            float mloc = -1e30f;
            #pragma unroll
            for (int k = 0; k < 8; k++) {
                vals[k] = sS[row*65 + g*8 + k];
                mloc = fmaxf(mloc, vals[k]);
            }
            #pragma unroll
            for (int w = 4; w >= 1; w >>= 1)
                mloc = fmaxf(mloc, __shfl_xor_sync(0xffffffffu, mloc, w, 8));
            const float mprev = sM[row];
            const float mnew  = fmaxf(mprev, mloc);
            float lsum = 0.f;
            #pragma unroll
            for (int k = 0; k < 8; k++) {
                const float p = __expf(vals[k] - mnew);
                lsum += p;
                sS[row*65 + g*8 + k] = p;
            }
            #pragma unroll
            for (int w = 4; w >= 1; w >>= 1)
                lsum += __shfl_xor_sync(0xffffffffu, lsum, w, 8);
            if (g == 0) {
                const float alpha = __expf(mprev - mnew);
                sA[row] = alpha;
                sL[row] = sL[row]*alpha + lsum;
                sM[row] = mnew;
            }
        }
        __syncthreads();

        // ---- rescale O ----
        const float al0 = sA[r0];
        const float al1 = sA[r0+1];
        #pragma unroll
        for (int k = 0; k < 32; k++) { O[0][k] *= al0; O[1][k] *= al1; }

        // ---- O += P @ V over 4 j-chunks of 16 ----
        for (int vc = 0; vc < 4; vc++) {
            __syncthreads();
            #pragma unroll
            for (int i = 0; i < 8; i++) {
                const int lin = (i*256 + tid) * 4;
                const int r = lin >> 9;      // 0..15
                const int c = lin & 511;
                *(float4*)&sKV[r*516 + c] =
                    *(const float4*)&Vg[(size_t)(j0 + vc*16 + r)*CH + c];
            }
            __syncthreads();
            #pragma unroll 2
            for (int j = 0; j < 16; j++) {
                const float p0 = sS[r0*65 + vc*16 + j];
                const float p1 = sS[(r0+1)*65 + vc*16 + j];
                const float* vrow = &sKV[j*516 + colg*4];
                #pragma unroll
                for (int k = 0; k < 8; k++) {
                    const float4 v4 = *(const float4*)&vrow[k*64];
                    O[0][k*4+0] += p0*v4.x; O[0][k*4+1] += p0*v4.y;
                    O[0][k*4+2] += p0*v4.z; O[0][k*4+3] += p0*v4.w;
                    O[1][k*4+0] += p1*v4.x; O[1][k*4+1] += p1*v4.y;
                    O[1][k*4+2] += p1*v4.z; O[1][k*4+3] += p1*v4.w;
                }
            }
        }
    }

    __syncthreads();
    const float inv0 = 1.0f / sL[r0];
    const float inv1 = 1.0f / sL[r0+1];
    const size_t base0 = ((size_t)(b*SEQ + q0 + r0))*1024 + 512;
    #pragma unroll
    for (int k = 0; k < 8; k++) {
        const int d = colg*4 + k*64;
        float4 o0, o1;
        o0.x = O[0][k*4+0]*inv0; o0.y = O[0][k*4+1]*inv0;
        o0.z = O[0][k*4+2]*inv0; o0.w = O[0][k*4+3]*inv0;
        o1.x = O[1][k*4+0]*inv1; o1.y = O[1][k*4+1]*inv1;
        o1.z = O[1][k*4+2]*inv1; o1.w = O[1][k*4+3]*inv1;
        *(float4*)&out[base0 + d]        = o0;
        *(float4*)&out[base0 + 1024 + d] = o1;
    }
}

// ---------------------------------------------------------------------------
// Kernel 3: copy x into out[..., 0:512]
// ---------------------------------------------------------------------------
__global__ __launch_bounds__(256) void copy_x_kernel(const float* __restrict__ x,
                                                     float* __restrict__ out)
{
    const size_t i = (size_t)blockIdx.x * blockDim.x + threadIdx.x; // float4 index
    const float4 v = ((const float4*)x)[i];
    const size_t lin = i * 4;
    const size_t row = lin >> 9;      // /512
    const size_t c   = lin & 511;
    *(float4*)&out[row*1024 + c] = v;
}

// ---------------------------------------------------------------------------
extern "C" void kernel_launch(void* const* d_in, const int* in_sizes, int n_in,
                              void* d_out, int out_size)
{
    const float* x  = (const float*)d_in[0];
    const float* Wq = (const float*)d_in[1];
    const float* bq = (const float*)d_in[2];
    const float* Wk = (const float*)d_in[3];
    const float* bk = (const float*)d_in[4];
    const float* Wv = (const float*)d_in[5];
    const float* bv = (const float*)d_in[6];
    float* out = (float*)d_out;

    cudaFuncSetAttribute(attn_kernel,
                         cudaFuncAttributeMaxDynamicSharedMemorySize, SMEM_BYTES);

    // QKV projections: grid (N/128=4, M/128=128, 3)
    qkv_gemm<<<dim3(4, 128, 3), 256>>>(x, Wq, bq, Wk, bk, Wv, bv);

    // Concat half: out[...,0:512] = x   (16384*512/4 float4s / 256 threads)
    copy_x_kernel<<<8192, 256>>>(x, out);

    // Attention: grid (T/32=64, B=8)
    attn_kernel<<<dim3(64, 8), 256, SMEM_BYTES>>>(out);
}

// round 13
// speedup vs baseline: 1.0537x; 1.0537x over previous
#include <cuda_runtime.h>
#include <math.h>

#define BATCH 8
#define SEQ   2048
#define CH    512
#define MTOT  (BATCH*SEQ)          // 16384
#define SCALE 0.04419417382415922f // 1/sqrt(512)

#define BR 32
#define BC 64

// Scratch for projected q,k,v (device globals: allocation-free per harness rules)
__device__ float g_q[(size_t)MTOT*CH];
__device__ float g_k[(size_t)MTOT*CH];
__device__ float g_v[(size_t)MTOT*CH];

// ---------------------------------------------------------------------------
// Kernel 1: QKV projection.  C_z = x @ W_z + b_z,  z = blockIdx.z in {q,k,v}
// Classic 128x128x8 SGEMM, 256 threads, 8x8 per-thread microtile.
// ---------------------------------------------------------------------------
__global__ __launch_bounds__(256) void qkv_gemm(
    const float* __restrict__ x,
    const float* __restrict__ Wq, const float* __restrict__ bq,
    const float* __restrict__ Wk, const float* __restrict__ bk,
    const float* __restrict__ Wv, const float* __restrict__ bv)
{
    __shared__ float As[8][128];
    __shared__ float Bs[8][128];

    const int z = blockIdx.z;
    const float* W    = (z == 0) ? Wq : (z == 1) ? Wk : Wv;
    const float* bias = (z == 0) ? bq : (z == 1) ? bk : bv;
    float* out        = (z == 0) ? g_q : (z == 1) ? g_k : g_v;

    const int bm = blockIdx.y * 128;
    const int bn = blockIdx.x * 128;
    const int tid = threadIdx.x;
    const int tx = tid & 15;        // 0..15 (col group)
    const int ty = tid >> 4;        // 0..15 (row group)

    const int a_row = tid >> 1;         // 0..127
    const int a_k4  = (tid & 1) * 4;    // 0 or 4
    const int b_k   = tid >> 5;         // 0..7
    const int b_n4  = (tid & 31) * 4;   // 0..124

    float acc[8][8];
    #pragma unroll
    for (int i = 0; i < 8; i++)
        #pragma unroll
        for (int j = 0; j < 8; j++) acc[i][j] = 0.f;

    for (int k0 = 0; k0 < CH; k0 += 8) {
        float4 av  = *(const float4*)&x[(size_t)(bm + a_row)*CH + k0 + a_k4];
        float4 bv4 = *(const float4*)&W[(size_t)(k0 + b_k)*CH + bn + b_n4];
        __syncthreads();   // protect prior-iteration smem reads
        As[a_k4+0][a_row] = av.x;
        As[a_k4+1][a_row] = av.y;
        As[a_k4+2][a_row] = av.z;
        As[a_k4+3][a_row] = av.w;
        *(float4*)&Bs[b_k][b_n4] = bv4;
        __syncthreads();
        #pragma unroll
        for (int k = 0; k < 8; k++) {
            float a[8], bb[8];
            *(float4*)&a[0]  = *(float4*)&As[k][ty*8];
            *(float4*)&a[4]  = *(float4*)&As[k][ty*8+4];
            *(float4*)&bb[0] = *(float4*)&Bs[k][tx*8];
            *(float4*)&bb[4] = *(float4*)&Bs[k][tx*8+4];
            #pragma unroll
            for (int i = 0; i < 8; i++)
                #pragma unroll
                for (int j = 0; j < 8; j++)
                    acc[i][j] += a[i] * bb[j];
        }
    }

    #pragma unroll
    for (int i = 0; i < 8; i++) {
        const int m = bm + ty*8 + i;
        #pragma unroll
        for (int j = 0; j < 8; j += 4) {
            const int n = bn + tx*8 + j;
            float4 o;
            o.x = acc[i][j+0] + bias[n+0];
            o.y = acc[i][j+1] + bias[n+1];
            o.z = acc[i][j+2] + bias[n+2];
            o.w = acc[i][j+3] + bias[n+3];
            *(float4*)&out[(size_t)m*CH + n] = o;
        }
    }
}

// ---------------------------------------------------------------------------
// Kernel 2: flash attention (fp32, causal), Br=32 q-rows per block, Bc=64.
// Q block resident in smem; K streamed in [64][128] d-chunks, V streamed in
// [16][512] j-chunks through a shared buffer. O in registers (2 rows x 32 d
// per thread). Online softmax, 8 threads per row.
// smem: sQ 32*516 | sKV 8256 | sS 32*65 | sM/sL/sA 32 each  = 107776 bytes
// ---------------------------------------------------------------------------
#define SMEM_FLOATS (32*516 + 8256 + 32*65 + 96)
#define SMEM_BYTES  (SMEM_FLOATS * 4)

__global__ __launch_bounds__(256, 2) void attn_kernel(float* __restrict__ out)
{
    extern __shared__ float smem[];
    float* sQ  = smem;                 // [32][516]
    float* sKV = sQ + 32*516;          // 8256 floats (K chunks [64][129] / V chunks [16][516])
    float* sS  = sKV + 8256;           // [32][65]
    float* sM  = sS + 32*65;
    float* sL  = sM + 32;
    float* sA  = sL + 32;

    const int b   = blockIdx.y;
    const int qb  = blockIdx.x;
    const int q0  = qb * BR;
    const int tid = threadIdx.x;

    const float* Qg = g_q + (size_t)b*SEQ*CH;
    const float* Kg = g_k + (size_t)b*SEQ*CH;
    const float* Vg = g_v + (size_t)b*SEQ*CH;

    // Load Q block (scaled by 1/sqrt(d))
    #pragma unroll
    for (int i = 0; i < 16; i++) {
        const int lin = (i*256 + tid) * 4;   // 0..16380
        const int r = lin >> 9;
        const int c = lin & 511;
        float4 v = *(const float4*)&Qg[(size_t)(q0 + r)*CH + c];
        v.x *= SCALE; v.y *= SCALE; v.z *= SCALE; v.w *= SCALE;
        *(float4*)&sQ[r*516 + c] = v;
    }
    if (tid < 32) { sM[tid] = -1e30f; sL[tid] = 0.f; }

    const int rowg = tid >> 4;   // 0..15
    const int colg = tid & 15;   // 0..15
    const int r0 = rowg * 2;

    float O[2][32];
    #pragma unroll
    for (int i = 0; i < 2; i++)
        #pragma unroll
        for (int k = 0; k < 32; k++) O[i][k] = 0.f;

    const int n_tiles = (q0 + BR + BC - 1) / BC;

    for (int t = 0; t < n_tiles; t++) {
        const int j0 = t * BC;
        float acc[2][4];
        #pragma unroll
        for (int i = 0; i < 2; i++)
            #pragma unroll
            for (int j = 0; j < 4; j++) acc[i][j] = 0.f;

        // ---- S = Q K^T accumulated over 4 d-chunks of 128 ----
        for (int cc = 0; cc < 4; cc++) {
            __syncthreads();  // protect prior consumers of sKV
            #pragma unroll
            for (int i = 0; i < 8; i++) {
                const int lin = (i*256 + tid) * 4;
                const int r = lin >> 7;      // /128 -> 0..63
                const int c = lin & 127;
                float4 v = *(const float4*)&Kg[(size_t)(j0 + r)*CH + cc*128 + c];
                float* p = &sKV[r*129 + c];
                p[0] = v.x; p[1] = v.y; p[2] = v.z; p[3] = v.w;
            }
            __syncthreads();
            const float* qb0 = &sQ[r0*516 + cc*128];
            const float* qb1 = qb0 + 516;
            const float* kb  = &sKV[(colg*4)*129];
            #pragma unroll 4
            for (int c = 0; c < 128; c++) {
                const float a0 = qb0[c];
                const float a1 = qb1[c];
                #pragma unroll
                for (int jj = 0; jj < 4; jj++) {
                    const float bb = kb[jj*129 + c];
                    acc[0][jj] += a0 * bb;
                    acc[1][jj] += a1 * bb;
                }
            }
        }

        // ---- causal mask + stage S ----
        #pragma unroll
        for (int i = 0; i < 2; i++) {
            const int qg = q0 + r0 + i;
            #pragma unroll
            for (int jj = 0; jj < 4; jj++) {
                const int jgl = j0 + colg*4 + jj;
                float v = acc[i][jj];
                if (jgl > qg) v = -1e30f;
                sS[(r0+i)*65 + colg*4 + jj] = v;
            }
        }
        __syncthreads();

        // ---- online softmax: 8 threads per row ----
        {
            const int row = tid >> 3;
            const int g   = tid & 7;
            float vals[8];
            float mloc = -1e30f;
            #pragma unroll
            for (int k = 0; k < 8; k++) {
                vals[k] = sS[row*65 + g*8 + k];
                mloc = fmaxf(mloc, vals[k]);
            }
            #pragma unroll
            for (int w = 4; w >= 1; w >>= 1)
                mloc = fmaxf(mloc, __shfl_xor_sync(0xffffffffu, mloc, w, 8));
            const float mprev = sM[row];
            const float mnew  = fmaxf(mprev, mloc);
            float lsum = 0.f;
            #pragma unroll
            for (int k = 0; k < 8; k++) {
                const float p = __expf(vals[k] - mnew);
                lsum += p;
                sS[row*65 + g*8 + k] = p;
            }
            #pragma unroll
            for (int w = 4; w >= 1; w >>= 1)
                lsum += __shfl_xor_sync(0xffffffffu, lsum, w, 8);
            if (g == 0) {
                const float alpha = __expf(mprev - mnew);
                sA[row] = alpha;
                sL[row] = sL[row]*alpha + lsum;
                sM[row] = mnew;
            }
        }
        __syncthreads();

        // ---- rescale O ----
        const float al0 = sA[r0];
        const float al1 = sA[r0+1];
        #pragma unroll
        for (int k = 0; k < 32; k++) { O[0][k] *= al0; O[1][k] *= al1; }

        // ---- O += P @ V over 4 j-chunks of 16 ----
        for (int vc = 0; vc < 4; vc++) {
            __syncthreads();
            #pragma unroll
            for (int i = 0; i < 8; i++) {
                const int lin = (i*256 + tid) * 4;
                const int r = lin >> 9;      // 0..15
                const int c = lin & 511;
                *(float4*)&sKV[r*516 + c] =
                    *(const float4*)&Vg[(size_t)(j0 + vc*16 + r)*CH + c];
            }
            __syncthreads();
            #pragma unroll 2
            for (int j = 0; j < 16; j++) {
                const float p0 = sS[r0*65 + vc*16 + j];
                const float p1 = sS[(r0+1)*65 + vc*16 + j];
                const float* vrow = &sKV[j*516 + colg*4];
                #pragma unroll
                for (int k = 0; k < 8; k++) {
                    const float4 v4 = *(const float4*)&vrow[k*64];
                    O[0][k*4+0] += p0*v4.x; O[0][k*4+1] += p0*v4.y;
                    O[0][k*4+2] += p0*v4.z; O[0][k*4+3] += p0*v4.w;
                    O[1][k*4+0] += p1*v4.x; O[1][k*4+1] += p1*v4.y;
                    O[1][k*4+2] += p1*v4.z; O[1][k*4+3] += p1*v4.w;
                }
            }
        }
    }

    __syncthreads();
    const float inv0 = 1.0f / sL[r0];
    const float inv1 = 1.0f / sL[r0+1];
    const size_t base0 = ((size_t)(b*SEQ + q0 + r0))*1024 + 512;
    #pragma unroll
    for (int k = 0; k < 8; k++) {
        const int d = colg*4 + k*64;
        float4 o0, o1;
        o0.x = O[0][k*4+0]*inv0; o0.y = O[0][k*4+1]*inv0;
        o0.z = O[0][k*4+2]*inv0; o0.w = O[0][k*4+3]*inv0;
        o1.x = O[1][k*4+0]*inv1; o1.y = O[1][k*4+1]*inv1;
        o1.z = O[1][k*4+2]*inv1; o1.w = O[1][k*4+3]*inv1;
        *(float4*)&out[base0 + d]        = o0;
        *(float4*)&out[base0 + 1024 + d] = o1;
    }
}

// ---------------------------------------------------------------------------
// Kernel 3: copy x into out[..., 0:512]
// ---------------------------------------------------------------------------
__global__ __launch_bounds__(256) void copy_x_kernel(const float* __restrict__ x,
                                                     float* __restrict__ out)
{
    const size_t i = (size_t)blockIdx.x * blockDim.x + threadIdx.x; // float4 index
    const float4 v = ((const float4*)x)[i];
    const size_t lin = i * 4;
    const size_t row = lin >> 9;      // /512
    const size_t c   = lin & 511;
    *(float4*)&out[row*1024 + c] = v;
}

// ---------------------------------------------------------------------------
extern "C" void kernel_launch(void* const* d_in, const int* in_sizes, int n_in,
                              void* d_out, int out_size)
{
    const float* x  = (const float*)d_in[0];
    const float* Wq = (const float*)d_in[1];
    const float* bq = (const float*)d_in[2];
    const float* Wk = (const float*)d_in[3];
    const float* bk = (const float*)d_in[4];
    const float* Wv = (const float*)d_in[5];
    const float* bv = (const float*)d_in[6];
    float* out = (float*)d_out;

    cudaFuncSetAttribute(attn_kernel,
                         cudaFuncAttributeMaxDynamicSharedMemorySize, SMEM_BYTES);

    // QKV projections: grid (N/128=4, M/128=128, 3)
    qkv_gemm<<<dim3(4, 128, 3), 256>>>(x, Wq, bq, Wk, bk, Wv, bv);

    // Concat half: out[...,0:512] = x   (16384*512/4 float4s / 256 threads)
    copy_x_kernel<<<8192, 256>>>(x, out);

    // Attention: grid (T/32=64, B=8)
    attn_kernel<<<dim3(64, 8), 256, SMEM_BYTES>>>(out);
}